// round 4
// baseline (speedup 1.0000x reference)
#include <cuda_runtime.h>
#include <math.h>

// Problem constants
#define SEQ   2048
#define BATCH 4
#define NH    4        // kv heads
#define HD    64       // head dim
#define IND   1024     // model dim
#define MROWS (BATCH*SEQ)   // 8192

// Scratch (device globals — no allocation allowed)
__device__ float g_Wqeff[IND * 256];       // [1024, 4*64] group-summed Wq
__device__ float g_QS[MROWS * 256];        // roped, group-summed Q projection [b*s, h*64+d]
__device__ float g_KV[MROWS * 512];        // cols 0..255 roped K, 256..511 V
__device__ float g_AO[MROWS * 256];        // attention output [b*s, h*64+d]

// inv_freq table: 10000^(-j/16) = 10^(-j/4), j = 0..15 (exact fp32 roundings)
__device__ const float c_invfreq[16] = {
    1.0f,
    0.5623413251903491f,
    0.31622776601683794f,
    0.17782794100389226f,
    0.1f,
    0.05623413251903491f,
    0.031622776601683791f,
    0.017782794100389227f,
    0.01f,
    0.005623413251903491f,
    0.0031622776601683794f,
    0.0017782794100389227f,
    0.001f,
    0.0005623413251903491f,
    0.00031622776601683794f,
    0.00017782794100389227f
};

// ---------------------------------------------------------------------------
// Wq_eff[i, h*64+d] = sum_g Wq[i, (h*4+g)*64 + d]
// (RoPE is linear in x with coefficients independent of head/group, and the
// reference einsum 'bghsd,bhad->bhsa' SUMS the group axis, so the 16-head Q
// projection collapses to 4 heads with group-summed weights.)
// ---------------------------------------------------------------------------
__global__ void wqeff_kernel(const float* __restrict__ Wq) {
    int e   = blockIdx.x * 256 + threadIdx.x;   // 0 .. 1024*256-1
    int i   = e >> 8;
    int col = e & 255;
    int h = col >> 6, d = col & 63;
    const float* base = Wq + (size_t)i * 1024 + (h * 4) * 64 + d;
    g_Wqeff[e] = base[0] + base[64] + base[128] + base[192];
}

// ---------------------------------------------------------------------------
// Generic fp32 tiled GEMM: C[M,N] = A[M,K] @ B[K,N], row-major, all dims
// multiples of tile sizes (true for every call here).
// BM=128, BN=64, BK=16, 256 threads, 8x4 per-thread microtile.
// Global->register prefetch double buffering across K-slabs.
// ---------------------------------------------------------------------------
__global__ __launch_bounds__(256) void gemm_kernel(
    const float* __restrict__ A, const float* __restrict__ Bm,
    float* __restrict__ C,
    int K, int lda, int ldb, int ldc)
{
    __shared__ __align__(16) float AsT[16][132];  // [k][row]
    __shared__ __align__(16) float Bs[16][68];    // [k][col]

    int tid = threadIdx.x;
    int m0 = blockIdx.y * 128;
    int n0 = blockIdx.x * 64;
    int tr = tid >> 4, tc = tid & 15;
    int r0 = tr * 8, c0 = tc * 4;

    // per-thread load coordinates
    int la_row0 = tid >> 2;            // A: rows for the two float4 loads
    int la_kq   = (tid & 3) * 4;
    int lb_k    = tid >> 4;            // B
    int lb_c    = (tid & 15) * 4;

    float acc[8][4];
    #pragma unroll
    for (int i = 0; i < 8; i++)
        #pragma unroll
        for (int j = 0; j < 4; j++) acc[i][j] = 0.f;

    // Prologue: fetch slab 0 into registers
    float4 pa0 = *(const float4*)&A[(size_t)(m0 + la_row0) * lda + la_kq];
    float4 pa1 = *(const float4*)&A[(size_t)(m0 + la_row0 + 64) * lda + la_kq];
    float4 pb  = *(const float4*)&Bm[(size_t)lb_k * ldb + n0 + lb_c];

    for (int k0 = 0; k0 < K; k0 += 16) {
        // Store current slab to smem
        AsT[la_kq + 0][la_row0] = pa0.x; AsT[la_kq + 1][la_row0] = pa0.y;
        AsT[la_kq + 2][la_row0] = pa0.z; AsT[la_kq + 3][la_row0] = pa0.w;
        AsT[la_kq + 0][la_row0 + 64] = pa1.x; AsT[la_kq + 1][la_row0 + 64] = pa1.y;
        AsT[la_kq + 2][la_row0 + 64] = pa1.z; AsT[la_kq + 3][la_row0 + 64] = pa1.w;
        *(float4*)&Bs[lb_k][lb_c] = pb;
        __syncthreads();

        // Prefetch next slab into registers (overlaps with FMA loop below)
        if (k0 + 16 < K) {
            pa0 = *(const float4*)&A[(size_t)(m0 + la_row0) * lda + k0 + 16 + la_kq];
            pa1 = *(const float4*)&A[(size_t)(m0 + la_row0 + 64) * lda + k0 + 16 + la_kq];
            pb  = *(const float4*)&Bm[(size_t)(k0 + 16 + lb_k) * ldb + n0 + lb_c];
        }

        #pragma unroll
        for (int kk = 0; kk < 16; kk++) {
            float4 a0 = *(float4*)&AsT[kk][r0];
            float4 a1 = *(float4*)&AsT[kk][r0 + 4];
            float4 b  = *(float4*)&Bs[kk][c0];
            float av[8] = {a0.x, a0.y, a0.z, a0.w, a1.x, a1.y, a1.z, a1.w};
            float bv[4] = {b.x, b.y, b.z, b.w};
            #pragma unroll
            for (int i = 0; i < 8; i++)
                #pragma unroll
                for (int j = 0; j < 4; j++)
                    acc[i][j] += av[i] * bv[j];
        }
        __syncthreads();
    }

    #pragma unroll
    for (int i = 0; i < 8; i++) {
        float4 v = make_float4(acc[i][0], acc[i][1], acc[i][2], acc[i][3]);
        *(float4*)&C[(size_t)(m0 + r0 + i) * ldc + n0 + c0] = v;
    }
}

// ---------------------------------------------------------------------------
// In-place N-D RoPE. One block per row (b*s), 128 threads = 4 heads * 32 pairs.
// Per head of 64: axis = pair>>4 (2 axes), freq index = pair&15.
// ---------------------------------------------------------------------------
__global__ void rope_kernel(float* __restrict__ buf, const int* __restrict__ coords, int ld) {
    int row = blockIdx.x;
    int t = threadIdx.x;        // 0..127
    int head = t >> 5;
    int pp   = t & 31;          // pair index within head
    int axis = pp >> 4;         // 2 axes
    int fi   = pp & 15;         // 16 freqs per axis

    float af = (float)coords[row * 2 + axis] * c_invfreq[fi];  // fp32 angle, like reference
    float sn, cs;
    sincosf(af, &sn, &cs);

    float* p = buf + (size_t)row * ld + head * 64 + pp * 2;
    float x1 = p[0], x2 = p[1];
    p[0] = x1 * cs - x2 * sn;
    p[1] = x1 * sn + x2 * cs;
}

// ---------------------------------------------------------------------------
// Flash attention, fp32. One block = 128 queries of one (b, h) pair.
// grid = (16, 16), 256 threads, 8x4 per-thread microtile (FMA-bound:
// 3 LDS.128 per 32 FMA -> crossbar 96 cyc < FMA 128 cyc per block per d).
// BQ=128, BK=64, D=64. Online softmax.
// Dynamic smem floats:
//   QsT[64][132] + KsT[64][68] + Vs[64][68] + PsT[64][132] + m/l/a[128 each]
//   = 8448 + 4352 + 4352 + 8448 + 384 = 25984 floats = 103936 bytes
// ---------------------------------------------------------------------------
#define BQ    128
#define QPAD  132
#define KPAD  68
#define OFF_K   (64 * QPAD)
#define OFF_V   (OFF_K + 64 * KPAD)
#define OFF_P   (OFF_V + 64 * KPAD)
#define OFF_M   (OFF_P + 64 * QPAD)
#define ATTN_SMEM_BYTES ((OFF_M + 3 * BQ) * 4)

__global__ __launch_bounds__(256) void attn_kernel() {
    extern __shared__ __align__(16) float sm[];
    float* QsT  = sm;             // [d][qrow]   stride QPAD
    float* KsT  = sm + OFF_K;     // [d][kcol]   stride KPAD
    float* Vs   = sm + OFF_V;     // [key][dim]  stride KPAD
    float* PsT  = sm + OFF_P;     // [key][qrow] stride QPAD
    float* mrow = sm + OFF_M;
    float* lrow = mrow + BQ;
    float* arow = lrow + BQ;

    int tid = threadIdx.x;
    int b = blockIdx.y >> 2, h = blockIdx.y & 3;
    int qbase = blockIdx.x * BQ;
    int tr = tid >> 4, tc = tid & 15;
    int r0 = tr * 8, c0 = tc * 4;

    // Load Q tile transposed: QsT[d][r], 128 rows x 64 dims = 2048 float4
    #pragma unroll
    for (int i = 0; i < 8; i++) {
        int idx = tid + i * 256;
        int r  = idx >> 4;              // 0..127
        int dq = (idx & 15) * 4;        // 0..60
        float4 v = *(const float4*)&g_QS[(size_t)(b * SEQ + qbase + r) * 256 + h * 64 + dq];
        QsT[(dq + 0) * QPAD + r] = v.x; QsT[(dq + 1) * QPAD + r] = v.y;
        QsT[(dq + 2) * QPAD + r] = v.z; QsT[(dq + 3) * QPAD + r] = v.w;
    }
    if (tid < BQ) { mrow[tid] = -INFINITY; lrow[tid] = 0.f; }

    float o[8][4];
    #pragma unroll
    for (int i = 0; i < 8; i++)
        #pragma unroll
        for (int j = 0; j < 4; j++) o[i][j] = 0.f;

    for (int kt = 0; kt < 32; kt++) {
        __syncthreads();   // protect smem reuse (and init visibility on 1st iter)
        int kb = b * SEQ + kt * 64;

        // Load K tile (transposed) and V tile: 64 rows each
        #pragma unroll
        for (int i = 0; i < 4; i++) {
            int idx = tid + i * 256;
            int r  = idx >> 4;          // 0..63
            int dq = (idx & 15) * 4;
            float4 v = *(const float4*)&g_KV[(size_t)(kb + r) * 512 + h * 64 + dq];
            KsT[(dq + 0) * KPAD + r] = v.x; KsT[(dq + 1) * KPAD + r] = v.y;
            KsT[(dq + 2) * KPAD + r] = v.z; KsT[(dq + 3) * KPAD + r] = v.w;
            float4 w = *(const float4*)&g_KV[(size_t)(kb + r) * 512 + 256 + h * 64 + dq];
            *(float4*)&Vs[r * KPAD + dq] = w;
        }
        __syncthreads();

        // S = Q @ K^T  (per-thread 8x4 microtile), scale by 1/8
        float s[8][4];
        #pragma unroll
        for (int i = 0; i < 8; i++)
            #pragma unroll
            for (int j = 0; j < 4; j++) s[i][j] = 0.f;

        #pragma unroll 4
        for (int d = 0; d < 64; d++) {
            float4 a0 = *(float4*)&QsT[d * QPAD + r0];
            float4 a1 = *(float4*)&QsT[d * QPAD + r0 + 4];
            float4 k  = *(float4*)&KsT[d * KPAD + c0];
            float qa[8] = {a0.x, a0.y, a0.z, a0.w, a1.x, a1.y, a1.z, a1.w};
            float ka[4] = {k.x, k.y, k.z, k.w};
            #pragma unroll
            for (int i = 0; i < 8; i++)
                #pragma unroll
                for (int j = 0; j < 4; j++)
                    s[i][j] += qa[i] * ka[j];
        }
        #pragma unroll
        for (int i = 0; i < 8; i++)
            #pragma unroll
            for (int j = 0; j < 4; j++) {
                s[i][j] *= 0.125f;
                PsT[(c0 + j) * QPAD + (r0 + i)] = s[i][j];   // raw scores
            }
        __syncthreads();

        // Stage A: row max + correction factor (128 rows, 128 threads)
        if (tid < BQ) {
            int r = tid;
            float m = mrow[r], mo = m;
            #pragma unroll 8
            for (int c = 0; c < 64; c++) m = fmaxf(m, PsT[c * QPAD + r]);
            mrow[r] = m;
            arow[r] = __expf(mo - m);   // exp(-inf)=0 on first tile
        }
        __syncthreads();

        // Stage B: exponentiate own entries, rescale O accumulator
        {
            float mn[8], al[8];
            #pragma unroll
            for (int i = 0; i < 8; i++) { mn[i] = mrow[r0 + i]; al[i] = arow[r0 + i]; }
            #pragma unroll
            for (int i = 0; i < 8; i++) {
                #pragma unroll
                for (int j = 0; j < 4; j++) {
                    PsT[(c0 + j) * QPAD + (r0 + i)] = __expf(s[i][j] - mn[i]);
                    o[i][j] *= al[i];
                }
            }
        }
        __syncthreads();

        // Stage C: row sums (128 threads), then PV by everyone (both read-only)
        if (tid < BQ) {
            int r = tid;
            float ssum = 0.f;
            #pragma unroll 8
            for (int c = 0; c < 64; c++) ssum += PsT[c * QPAD + r];
            lrow[r] = lrow[r] * arow[r] + ssum;
        }
        #pragma unroll 4
        for (int j = 0; j < 64; j++) {
            float4 p0 = *(float4*)&PsT[j * QPAD + r0];
            float4 p1 = *(float4*)&PsT[j * QPAD + r0 + 4];
            float4 v  = *(float4*)&Vs[j * KPAD + c0];
            float pa[8] = {p0.x, p0.y, p0.z, p0.w, p1.x, p1.y, p1.z, p1.w};
            float va[4] = {v.x, v.y, v.z, v.w};
            #pragma unroll
            for (int i = 0; i < 8; i++)
                #pragma unroll
                for (int k = 0; k < 4; k++)
                    o[i][k] += pa[i] * va[k];
        }
    }
    __syncthreads();

    #pragma unroll
    for (int i = 0; i < 8; i++) {
        float inv = 1.0f / lrow[r0 + i];
        float4 w = make_float4(o[i][0] * inv, o[i][1] * inv, o[i][2] * inv, o[i][3] * inv);
        *(float4*)&g_AO[(size_t)(b * SEQ + qbase + r0 + i) * 256 + h * 64 + c0] = w;
    }
}

// ---------------------------------------------------------------------------
extern "C" void kernel_launch(void* const* d_in, const int* in_sizes, int n_in,
                              void* d_out, int out_size) {
    const float* q   = (const float*)d_in[0];
    const int*   qc  = (const int*)  d_in[1];
    const float* kv  = (const float*)d_in[2];
    const int*   kvc = (const int*)  d_in[3];
    const float* Wq  = (const float*)d_in[4];
    const float* Wk  = (const float*)d_in[5];
    const float* Wv  = (const float*)d_in[6];
    const float* Wo  = (const float*)d_in[7];
    float* out = (float*)d_out;

    float *pWqeff, *pQS, *pKV, *pAO;
    cudaGetSymbolAddress((void**)&pWqeff, g_Wqeff);
    cudaGetSymbolAddress((void**)&pQS,    g_QS);
    cudaGetSymbolAddress((void**)&pKV,    g_KV);
    cudaGetSymbolAddress((void**)&pAO,    g_AO);

    // 1) group-summed Wq
    wqeff_kernel<<<1024, 256>>>(Wq);

    // 2) projections: QS = q @ Wq_eff ; KV[:, :256] = kv @ Wk ; KV[:, 256:] = kv @ Wv
    gemm_kernel<<<dim3(256 / 64, MROWS / 128), 256>>>(q,  pWqeff, pQS,       1024, 1024, 256, 256);
    gemm_kernel<<<dim3(256 / 64, MROWS / 128), 256>>>(kv, Wk,     pKV,       1024, 1024, 256, 512);
    gemm_kernel<<<dim3(256 / 64, MROWS / 128), 256>>>(kv, Wv,     pKV + 256, 1024, 1024, 256, 512);

    // 3) RoPE (in place)
    rope_kernel<<<MROWS, 128>>>(pQS, qc,  256);
    rope_kernel<<<MROWS, 128>>>(pKV, kvc, 512);

    // 4) attention (16 (b,h) pairs x 16 query tiles of 128)
    cudaFuncSetAttribute(attn_kernel, cudaFuncAttributeMaxDynamicSharedMemorySize, ATTN_SMEM_BYTES);
    attn_kernel<<<dim3(SEQ / BQ, 16), 256, ATTN_SMEM_BYTES>>>();

    // 5) output projection: out = AO @ Wo
    gemm_kernel<<<dim3(1024 / 64, MROWS / 128), 256>>>(pAO, Wo, out, 256, 256, 1024, 1024);
}

// round 11
// speedup vs baseline: 1.2049x; 1.2049x over previous
#include <cuda_runtime.h>
#include <cuda_bf16.h>
#include <math.h>
#include <cstdint>

// Problem constants
#define SEQ   2048
#define BATCH 4
#define NH    4        // kv heads
#define HD    64       // head dim
#define IND   1024     // model dim
#define MROWS (BATCH*SEQ)   // 8192

// ---------------------------------------------------------------------------
// Scratch (device globals — no allocation allowed)
// ---------------------------------------------------------------------------
__device__ float g_Wqeff[IND * 256];          // [1024, 256] group-summed Wq
__device__ float g_QS[MROWS * 256];           // roped Q projection [b*s, h*64+d]
__device__ float g_KV[MROWS * 512];           // 0..255 roped K, 256..511 V
__device__ float g_AO[MROWS * 256];           // attention output

// bf16 split buffers
__device__ __nv_bfloat16 g_Ahi[MROWS * IND];  // activation hi  (reused q/kv/AO)
__device__ __nv_bfloat16 g_Alo[MROWS * IND];  // activation lo
__device__ __nv_bfloat16 g_WqT_hi[256 * 1024],  g_WqT_lo[256 * 1024];   // [N,K]
__device__ __nv_bfloat16 g_WkvT_hi[512 * 1024], g_WkvT_lo[512 * 1024];  // [N,K] rows 0-255 K, 256-511 V
__device__ __nv_bfloat16 g_WoT_hi[1024 * 256],  g_WoT_lo[1024 * 256];   // [N,K]

// inv_freq table: 10000^(-j/16) = 10^(-j/4)
__device__ const float c_invfreq[16] = {
    1.0f, 0.5623413251903491f, 0.31622776601683794f, 0.17782794100389226f,
    0.1f, 0.05623413251903491f, 0.031622776601683791f, 0.017782794100389227f,
    0.01f, 0.005623413251903491f, 0.0031622776601683794f, 0.0017782794100389227f,
    0.001f, 0.0005623413251903491f, 0.00031622776601683794f, 0.00017782794100389227f
};

// ---------------------------------------------------------------------------
// Warp MMA helpers (base-ISA: ldmatrix sm_75+, bf16 mma.sync sm_80+ — these
// compile for plain sm_103 unlike tcgen05/.cta_group which need sm_103a PTX)
// ---------------------------------------------------------------------------
__device__ __forceinline__ uint32_t smem_u32(const void* p) {
    uint32_t a;
    asm("{ .reg .u64 t; cvta.to.shared.u64 t, %1; cvt.u32.u64 %0, t; }" : "=r"(a) : "l"(p));
    return a;
}
__device__ __forceinline__ void ldmx4(uint32_t* r, uint32_t addr) {
    asm volatile("ldmatrix.sync.aligned.m8n8.x4.shared.b16 {%0,%1,%2,%3}, [%4];"
                 : "=r"(r[0]), "=r"(r[1]), "=r"(r[2]), "=r"(r[3]) : "r"(addr));
}
__device__ __forceinline__ void mma_bf16(float* c, const uint32_t* a, const uint32_t* b) {
    asm volatile("mma.sync.aligned.m16n8k16.row.col.f32.bf16.bf16.f32 "
                 "{%0,%1,%2,%3}, {%4,%5,%6,%7}, {%8,%9}, {%0,%1,%2,%3};"
                 : "+f"(c[0]), "+f"(c[1]), "+f"(c[2]), "+f"(c[3])
                 : "r"(a[0]), "r"(a[1]), "r"(a[2]), "r"(a[3]), "r"(b[0]), "r"(b[1]));
}

// ---------------------------------------------------------------------------
// Wq_eff[i, h*64+d] = sum_g Wq[i, (h*4+g)*64 + d]   (group axis is summed in
// the reference einsum; RoPE is linear -> fold into the projection weight)
// ---------------------------------------------------------------------------
__global__ void wqeff_kernel(const float* __restrict__ Wq) {
    int e = blockIdx.x * 256 + threadIdx.x;
    int i = e >> 8, col = e & 255;
    int h = col >> 6, d = col & 63;
    const float* base = Wq + (size_t)i * 1024 + (h * 4) * 64 + d;
    g_Wqeff[e] = base[0] + base[64] + base[128] + base[192];
}

// ---------------------------------------------------------------------------
// Activation split: X fp32 [n] -> hi/lo bf16
// ---------------------------------------------------------------------------
__global__ void asplit_kernel(const float* __restrict__ X, int n) {
    int i = blockIdx.x * 256 + threadIdx.x;
    if (i < n) {
        float x = X[i];
        __nv_bfloat16 h = __float2bfloat16(x);
        g_Ahi[i] = h;
        g_Alo[i] = __float2bfloat16(x - __bfloat162float(h));
    }
}

// ---------------------------------------------------------------------------
// Weight transpose+split: W [K,N] fp32 -> T_hi/T_lo [N(+off), K] bf16
// ---------------------------------------------------------------------------
__global__ void wsplit_t_kernel(const float* __restrict__ W,
                                __nv_bfloat16* __restrict__ thi,
                                __nv_bfloat16* __restrict__ tlo,
                                int K, int N, int row_off) {
    int i = blockIdx.x * 256 + threadIdx.x;
    if (i < K * N) {
        int k = i / N, n = i % N;
        float x = W[i];
        __nv_bfloat16 h = __float2bfloat16(x);
        size_t o = (size_t)(row_off + n) * K + k;
        thi[o] = h;
        tlo[o] = __float2bfloat16(x - __bfloat162float(h));
    }
}

// ---------------------------------------------------------------------------
// HMMA GEMM: C[M,N] = A@B^T with 3-term bf16 split (Ahi*Bhi + Ahi*Blo + Alo*Bhi).
// A(hi/lo): [M,K] bf16 row-major. B(hi/lo): [N,K] bf16 row-major (k-contig = "col").
// Block tile 128x64, K chunks of 64. 8 warps in 4(m) x 2(n); warp tile 32x32.
// smem rows padded to 72 bf16 (144 B): ldmatrix bank-shift 4/row, conflict-free.
// grid = (N/64, M/128), 256 threads.
// ---------------------------------------------------------------------------
#define HS_PAD  72
#define HS_AHI  0
#define HS_ALO  (128 * HS_PAD)               // 9216 elems
#define HS_BHI  (2 * 128 * HS_PAD)           // 18432
#define HS_BLO  (2 * 128 * HS_PAD + 64 * HS_PAD)
#define HS_TOTAL_BYTES ((2 * 128 * HS_PAD + 2 * 64 * HS_PAD) * 2)   // 55296

__global__ __launch_bounds__(256) void hmma_gemm_kernel(
    const __nv_bfloat16* __restrict__ Ahi, const __nv_bfloat16* __restrict__ Alo,
    const __nv_bfloat16* __restrict__ Bhi, const __nv_bfloat16* __restrict__ Blo,
    float* __restrict__ C, int K, int ldc)
{
    extern __shared__ __align__(16) __nv_bfloat16 hsm[];
    uint32_t smb = smem_u32(hsm);
    int tid = threadIdx.x, lane = tid & 31, warp = tid >> 5;
    int wm = (warp & 3) * 32;        // warp m offset in tile
    int wn = (warp >> 2) * 32;       // warp n offset in tile
    int n0 = blockIdx.x * 64, m0 = blockIdx.y * 128;

    float acc[2][4][4];
    #pragma unroll
    for (int i = 0; i < 2; i++)
        #pragma unroll
        for (int j = 0; j < 4; j++)
            #pragma unroll
            for (int k = 0; k < 4; k++) acc[i][j][k] = 0.f;

    uint32_t* smA_hi = (uint32_t*)(hsm + HS_AHI);
    uint32_t* smA_lo = (uint32_t*)(hsm + HS_ALO);
    uint32_t* smB_hi = (uint32_t*)(hsm + HS_BHI);
    uint32_t* smB_lo = (uint32_t*)(hsm + HS_BLO);
    int rs = K >> 1;   // global row stride in u32

    // ldmatrix base addresses (byte offsets within smem)
    //  A x4: rows (lane&15), k-half (lane>>4)*8
    int aRow = lane & 15, aKoff = (lane >> 4) << 3;
    //  B x4: g=lane>>3 -> matrices {n0-7,k0},{n0-7,k8},{n8-15,k0},{n8-15,k8}
    int g = lane >> 3;
    int bRow = ((g >> 1) << 3) + (lane & 7), bKoff = (g & 1) << 3;

    int nchunks = K >> 6;
    for (int c = 0; c < nchunks; c++) {
        __syncthreads();   // protect smem reuse from previous chunk
        // Fill A: 128 rows x 32 u32, hi+lo
        const uint32_t* srcAh = (const uint32_t*)(Ahi + (size_t)m0 * K + c * 64);
        const uint32_t* srcAl = (const uint32_t*)(Alo + (size_t)m0 * K + c * 64);
        #pragma unroll
        for (int i = tid; i < 4096; i += 256) {
            int r = i >> 5, kp = i & 31;
            smA_hi[r * 36 + kp] = srcAh[(size_t)r * rs + kp];
            smA_lo[r * 36 + kp] = srcAl[(size_t)r * rs + kp];
        }
        // Fill B: 64 rows x 32 u32, hi+lo
        const uint32_t* srcBh = (const uint32_t*)(Bhi + (size_t)n0 * K + c * 64);
        const uint32_t* srcBl = (const uint32_t*)(Blo + (size_t)n0 * K + c * 64);
        #pragma unroll
        for (int i = tid; i < 2048; i += 256) {
            int r = i >> 5, kp = i & 31;
            smB_hi[r * 36 + kp] = srcBh[(size_t)r * rs + kp];
            smB_lo[r * 36 + kp] = srcBl[(size_t)r * rs + kp];
        }
        __syncthreads();

        #pragma unroll
        for (int ks = 0; ks < 4; ks++) {
            int k0 = ks * 16;
            uint32_t ah[2][4], al[2][4], bh[4][2], bl[4][2];
            #pragma unroll
            for (int mt = 0; mt < 2; mt++) {
                uint32_t off = (uint32_t)(((wm + mt * 16 + aRow) * HS_PAD + k0 + aKoff) * 2);
                ldmx4(ah[mt], smb + HS_AHI * 2 + off);
                ldmx4(al[mt], smb + HS_ALO * 2 + off);
            }
            #pragma unroll
            for (int half = 0; half < 2; half++) {
                uint32_t off = (uint32_t)(((wn + half * 16 + bRow) * HS_PAD + k0 + bKoff) * 2);
                uint32_t t[4];
                ldmx4(t, smb + HS_BHI * 2 + off);
                bh[half * 2][0] = t[0]; bh[half * 2][1] = t[1];
                bh[half * 2 + 1][0] = t[2]; bh[half * 2 + 1][1] = t[3];
                ldmx4(t, smb + HS_BLO * 2 + off);
                bl[half * 2][0] = t[0]; bl[half * 2][1] = t[1];
                bl[half * 2 + 1][0] = t[2]; bl[half * 2 + 1][1] = t[3];
            }
            #pragma unroll
            for (int mt = 0; mt < 2; mt++)
                #pragma unroll
                for (int nt = 0; nt < 4; nt++) {
                    mma_bf16(acc[mt][nt], ah[mt], bh[nt]);
                    mma_bf16(acc[mt][nt], ah[mt], bl[nt]);
                    mma_bf16(acc[mt][nt], al[mt], bh[nt]);
                }
        }
    }

    // Epilogue: c0,c1 -> (row=gid, col=tig*2+0/1); c2,c3 -> (row=gid+8, ...)
    int gid = lane >> 2, tig = lane & 3;
    #pragma unroll
    for (int mt = 0; mt < 2; mt++) {
        int row = m0 + wm + mt * 16 + gid;
        #pragma unroll
        for (int nt = 0; nt < 4; nt++) {
            int col = n0 + wn + nt * 8 + tig * 2;
            *(float2*)&C[(size_t)row * ldc + col]       = make_float2(acc[mt][nt][0], acc[mt][nt][1]);
            *(float2*)&C[(size_t)(row + 8) * ldc + col] = make_float2(acc[mt][nt][2], acc[mt][nt][3]);
        }
    }
}

// ---------------------------------------------------------------------------
// In-place N-D RoPE (unchanged, passing)
// ---------------------------------------------------------------------------
__global__ void rope_kernel(float* __restrict__ buf, const int* __restrict__ coords, int ld) {
    int row = blockIdx.x;
    int t = threadIdx.x;
    int head = t >> 5;
    int pp   = t & 31;
    int axis = pp >> 4;
    int fi   = pp & 15;

    float af = (float)coords[row * 2 + axis] * c_invfreq[fi];
    float sn, cs;
    sincosf(af, &sn, &cs);

    float* p = buf + (size_t)row * ld + head * 64 + pp * 2;
    float x1 = p[0], x2 = p[1];
    p[0] = x1 * cs - x2 * sn;
    p[1] = x1 * sn + x2 * cs;
}

// ---------------------------------------------------------------------------
// Flash attention, fp32 (unchanged from passing R4 kernel).
// BQ=128, BK=64, D=64, 256 threads, 8x4 microtile, online softmax.
// ---------------------------------------------------------------------------
#define BQ    128
#define QPAD  132
#define KPAD  68
#define OFF_K   (64 * QPAD)
#define OFF_V   (OFF_K + 64 * KPAD)
#define OFF_P   (OFF_V + 64 * KPAD)
#define OFF_M   (OFF_P + 64 * QPAD)
#define ATTN_SMEM_BYTES ((OFF_M + 3 * BQ) * 4)

__global__ __launch_bounds__(256) void attn_kernel() {
    extern __shared__ __align__(16) float sm[];
    float* QsT  = sm;
    float* KsT  = sm + OFF_K;
    float* Vs   = sm + OFF_V;
    float* PsT  = sm + OFF_P;
    float* mrow = sm + OFF_M;
    float* lrow = mrow + BQ;
    float* arow = lrow + BQ;

    int tid = threadIdx.x;
    int b = blockIdx.y >> 2, h = blockIdx.y & 3;
    int qbase = blockIdx.x * BQ;
    int tr = tid >> 4, tc = tid & 15;
    int r0 = tr * 8, c0 = tc * 4;

    #pragma unroll
    for (int i = 0; i < 8; i++) {
        int idx = tid + i * 256;
        int r  = idx >> 4;
        int dq = (idx & 15) * 4;
        float4 v = *(const float4*)&g_QS[(size_t)(b * SEQ + qbase + r) * 256 + h * 64 + dq];
        QsT[(dq + 0) * QPAD + r] = v.x; QsT[(dq + 1) * QPAD + r] = v.y;
        QsT[(dq + 2) * QPAD + r] = v.z; QsT[(dq + 3) * QPAD + r] = v.w;
    }
    if (tid < BQ) { mrow[tid] = -INFINITY; lrow[tid] = 0.f; }

    float o[8][4];
    #pragma unroll
    for (int i = 0; i < 8; i++)
        #pragma unroll
        for (int j = 0; j < 4; j++) o[i][j] = 0.f;

    for (int kt = 0; kt < 32; kt++) {
        __syncthreads();
        int kb = b * SEQ + kt * 64;

        #pragma unroll
        for (int i = 0; i < 4; i++) {
            int idx = tid + i * 256;
            int r  = idx >> 4;
            int dq = (idx & 15) * 4;
            float4 v = *(const float4*)&g_KV[(size_t)(kb + r) * 512 + h * 64 + dq];
            KsT[(dq + 0) * KPAD + r] = v.x; KsT[(dq + 1) * KPAD + r] = v.y;
            KsT[(dq + 2) * KPAD + r] = v.z; KsT[(dq + 3) * KPAD + r] = v.w;
            float4 w = *(const float4*)&g_KV[(size_t)(kb + r) * 512 + 256 + h * 64 + dq];
            *(float4*)&Vs[r * KPAD + dq] = w;
        }
        __syncthreads();

        float s[8][4];
        #pragma unroll
        for (int i = 0; i < 8; i++)
            #pragma unroll
            for (int j = 0; j < 4; j++) s[i][j] = 0.f;

        #pragma unroll 4
        for (int d = 0; d < 64; d++) {
            float4 a0 = *(float4*)&QsT[d * QPAD + r0];
            float4 a1 = *(float4*)&QsT[d * QPAD + r0 + 4];
            float4 k  = *(float4*)&KsT[d * KPAD + c0];
            float qa[8] = {a0.x, a0.y, a0.z, a0.w, a1.x, a1.y, a1.z, a1.w};
            float ka[4] = {k.x, k.y, k.z, k.w};
            #pragma unroll
            for (int i = 0; i < 8; i++)
                #pragma unroll
                for (int j = 0; j < 4; j++)
                    s[i][j] += qa[i] * ka[j];
        }
        #pragma unroll
        for (int i = 0; i < 8; i++)
            #pragma unroll
            for (int j = 0; j < 4; j++) {
                s[i][j] *= 0.125f;
                PsT[(c0 + j) * QPAD + (r0 + i)] = s[i][j];
            }
        __syncthreads();

        if (tid < BQ) {
            int r = tid;
            float m = mrow[r], mo = m;
            #pragma unroll 8
            for (int c = 0; c < 64; c++) m = fmaxf(m, PsT[c * QPAD + r]);
            mrow[r] = m;
            arow[r] = __expf(mo - m);
        }
        __syncthreads();

        {
            float mn[8], al[8];
            #pragma unroll
            for (int i = 0; i < 8; i++) { mn[i] = mrow[r0 + i]; al[i] = arow[r0 + i]; }
            #pragma unroll
            for (int i = 0; i < 8; i++) {
                #pragma unroll
                for (int j = 0; j < 4; j++) {
                    PsT[(c0 + j) * QPAD + (r0 + i)] = __expf(s[i][j] - mn[i]);
                    o[i][j] *= al[i];
                }
            }
        }
        __syncthreads();

        if (tid < BQ) {
            int r = tid;
            float ssum = 0.f;
            #pragma unroll 8
            for (int c = 0; c < 64; c++) ssum += PsT[c * QPAD + r];
            lrow[r] = lrow[r] * arow[r] + ssum;
        }
        #pragma unroll 4
        for (int j = 0; j < 64; j++) {
            float4 p0 = *(float4*)&PsT[j * QPAD + r0];
            float4 p1 = *(float4*)&PsT[j * QPAD + r0 + 4];
            float4 v  = *(float4*)&Vs[j * KPAD + c0];
            float pa[8] = {p0.x, p0.y, p0.z, p0.w, p1.x, p1.y, p1.z, p1.w};
            float va[4] = {v.x, v.y, v.z, v.w};
            #pragma unroll
            for (int i = 0; i < 8; i++)
                #pragma unroll
                for (int k = 0; k < 4; k++)
                    o[i][k] += pa[i] * va[k];
        }
    }
    __syncthreads();

    #pragma unroll
    for (int i = 0; i < 8; i++) {
        float inv = 1.0f / lrow[r0 + i];
        float4 w = make_float4(o[i][0] * inv, o[i][1] * inv, o[i][2] * inv, o[i][3] * inv);
        *(float4*)&g_AO[(size_t)(b * SEQ + qbase + r0 + i) * 256 + h * 64 + c0] = w;
    }
}

// ---------------------------------------------------------------------------
extern "C" void kernel_launch(void* const* d_in, const int* in_sizes, int n_in,
                              void* d_out, int out_size) {
    const float* q   = (const float*)d_in[0];
    const int*   qc  = (const int*)  d_in[1];
    const float* kv  = (const float*)d_in[2];
    const int*   kvc = (const int*)  d_in[3];
    const float* Wq  = (const float*)d_in[4];
    const float* Wk  = (const float*)d_in[5];
    const float* Wv  = (const float*)d_in[6];
    const float* Wo  = (const float*)d_in[7];
    float* out = (float*)d_out;

    float *pWqeff, *pQS, *pKV, *pAO;
    cudaGetSymbolAddress((void**)&pWqeff, g_Wqeff);
    cudaGetSymbolAddress((void**)&pQS,    g_QS);
    cudaGetSymbolAddress((void**)&pKV,    g_KV);
    cudaGetSymbolAddress((void**)&pAO,    g_AO);
    __nv_bfloat16 *pAhi, *pAlo, *pWqTh, *pWqTl, *pWkvTh, *pWkvTl, *pWoTh, *pWoTl;
    cudaGetSymbolAddress((void**)&pAhi,   g_Ahi);
    cudaGetSymbolAddress((void**)&pAlo,   g_Alo);
    cudaGetSymbolAddress((void**)&pWqTh,  g_WqT_hi);
    cudaGetSymbolAddress((void**)&pWqTl,  g_WqT_lo);
    cudaGetSymbolAddress((void**)&pWkvTh, g_WkvT_hi);
    cudaGetSymbolAddress((void**)&pWkvTl, g_WkvT_lo);
    cudaGetSymbolAddress((void**)&pWoTh,  g_WoT_hi);
    cudaGetSymbolAddress((void**)&pWoTl,  g_WoT_lo);

    cudaFuncSetAttribute(hmma_gemm_kernel, cudaFuncAttributeMaxDynamicSharedMemorySize, HS_TOTAL_BYTES);
    cudaFuncSetAttribute(attn_kernel,      cudaFuncAttributeMaxDynamicSharedMemorySize, ATTN_SMEM_BYTES);

    // 1) weight prep: group-sum Wq, then transpose+split all weights
    wqeff_kernel<<<1024, 256>>>(Wq);
    wsplit_t_kernel<<<(1024 * 256 + 255) / 256, 256>>>(pWqeff, pWqTh, pWqTl, 1024, 256, 0);
    wsplit_t_kernel<<<(1024 * 256 + 255) / 256, 256>>>(Wk, pWkvTh, pWkvTl, 1024, 256, 0);
    wsplit_t_kernel<<<(1024 * 256 + 255) / 256, 256>>>(Wv, pWkvTh, pWkvTl, 1024, 256, 256);
    wsplit_t_kernel<<<(256 * 1024 + 255) / 256, 256>>>(Wo, pWoTh, pWoTl, 256, 1024, 0);

    // 2) KV projections (fused, N=512): g_KV = kv @ [Wk|Wv]
    asplit_kernel<<<(MROWS * 1024 + 255) / 256, 256>>>(kv, MROWS * 1024);
    hmma_gemm_kernel<<<dim3(8, 64), 256, HS_TOTAL_BYTES>>>(pAhi, pAlo, pWkvTh, pWkvTl, pKV, 1024, 512);

    // 3) Q projection (group-summed, N=256): g_QS = q @ Wq_eff
    asplit_kernel<<<(MROWS * 1024 + 255) / 256, 256>>>(q, MROWS * 1024);
    hmma_gemm_kernel<<<dim3(4, 64), 256, HS_TOTAL_BYTES>>>(pAhi, pAlo, pWqTh, pWqTl, pQS, 1024, 256);

    // 4) RoPE (in place)
    rope_kernel<<<MROWS, 128>>>(pQS, qc,  256);
    rope_kernel<<<MROWS, 128>>>(pKV, kvc, 512);

    // 5) attention
    attn_kernel<<<dim3(SEQ / BQ, 16), 256, ATTN_SMEM_BYTES>>>();

    // 6) output projection: out = AO @ Wo  (K=256, N=1024)
    asplit_kernel<<<(MROWS * 256 + 255) / 256, 256>>>(pAO, MROWS * 256);
    hmma_gemm_kernel<<<dim3(16, 64), 256, HS_TOTAL_BYTES>>>(pAhi, pAlo, pWoTh, pWoTl, out, 256, 1024);
}

// round 14
// speedup vs baseline: 2.0140x; 1.6715x over previous
#include <cuda_runtime.h>
#include <cuda_bf16.h>
#include <math.h>
#include <cstdint>

// Problem constants
#define SEQ   2048
#define BATCH 4
#define NH    4        // kv heads
#define HD    64       // head dim
#define IND   1024     // model dim
#define MROWS (BATCH*SEQ)   // 8192

// ---------------------------------------------------------------------------
// Scratch (device globals — no allocation allowed)
// ---------------------------------------------------------------------------
__device__ float g_Wqeff[IND * 256];          // [1024, 256] group-summed Wq
__device__ float g_QS[MROWS * 256];           // Q projection (pre-rope) [b*s, h*64+d]
__device__ float g_KV[MROWS * 512];           // 0..255 K (pre-rope), 256..511 V
__device__ float g_AO[MROWS * 256];           // attention output

// bf16 split buffers (g_Ahi/g_Alo double as attention-input regions:
//  [0,2M): Q hi/lo   [2M,4M): K hi/lo   [4M,6M): Vt hi/lo)
__device__ __nv_bfloat16 g_Ahi[MROWS * IND];
__device__ __nv_bfloat16 g_Alo[MROWS * IND];
__device__ __nv_bfloat16 g_WqT_hi[256 * 1024],  g_WqT_lo[256 * 1024];   // [N,K]
__device__ __nv_bfloat16 g_WkvT_hi[512 * 1024], g_WkvT_lo[512 * 1024];  // [N,K]
__device__ __nv_bfloat16 g_WoT_hi[1024 * 256],  g_WoT_lo[1024 * 256];   // [N,K]

// inv_freq table: 10000^(-j/16) = 10^(-j/4)
__device__ const float c_invfreq[16] = {
    1.0f, 0.5623413251903491f, 0.31622776601683794f, 0.17782794100389226f,
    0.1f, 0.05623413251903491f, 0.031622776601683791f, 0.017782794100389227f,
    0.01f, 0.005623413251903491f, 0.0031622776601683794f, 0.0017782794100389227f,
    0.001f, 0.0005623413251903491f, 0.00031622776601683794f, 0.00017782794100389227f
};

// ---------------------------------------------------------------------------
// Warp MMA helpers (base-ISA only; compile for plain sm_103)
// ---------------------------------------------------------------------------
__device__ __forceinline__ uint32_t smem_u32(const void* p) {
    uint32_t a;
    asm("{ .reg .u64 t; cvta.to.shared.u64 t, %1; cvt.u32.u64 %0, t; }" : "=r"(a) : "l"(p));
    return a;
}
__device__ __forceinline__ void ldmx4(uint32_t* r, uint32_t addr) {
    asm volatile("ldmatrix.sync.aligned.m8n8.x4.shared.b16 {%0,%1,%2,%3}, [%4];"
                 : "=r"(r[0]), "=r"(r[1]), "=r"(r[2]), "=r"(r[3]) : "r"(addr));
}
__device__ __forceinline__ void mma_bf16(float* c, const uint32_t* a, const uint32_t* b) {
    asm volatile("mma.sync.aligned.m16n8k16.row.col.f32.bf16.bf16.f32 "
                 "{%0,%1,%2,%3}, {%4,%5,%6,%7}, {%8,%9}, {%0,%1,%2,%3};"
                 : "+f"(c[0]), "+f"(c[1]), "+f"(c[2]), "+f"(c[3])
                 : "r"(a[0]), "r"(a[1]), "r"(a[2]), "r"(a[3]), "r"(b[0]), "r"(b[1]));
}
// pack bf16x2: low half = lo_elem, high half = hi_elem (round-to-nearest)
__device__ __forceinline__ uint32_t cvt_pack(float lo_elem, float hi_elem) {
    uint32_t d;
    asm("cvt.rn.bf16x2.f32 %0, %1, %2;" : "=r"(d) : "f"(hi_elem), "f"(lo_elem));
    return d;
}
// truncation-pack: take high 16 bits of each fp32 (exact hi-part of split)
__device__ __forceinline__ uint32_t prmt_pack(float lo_elem, float hi_elem) {
    uint32_t d;
    asm("prmt.b32 %0, %1, %2, 0x7632;" : "=r"(d)
        : "r"(__float_as_uint(lo_elem)), "r"(__float_as_uint(hi_elem)));
    return d;
}
__device__ __forceinline__ float trunc_bf(float x) {
    return __uint_as_float(__float_as_uint(x) & 0xffff0000u);
}

// ---------------------------------------------------------------------------
// Wq_eff[i, h*64+d] = sum_g Wq[i, (h*4+g)*64 + d]  (group axis summed in the
// reference einsum; RoPE is linear -> fold into projection weight)
// ---------------------------------------------------------------------------
__global__ void wqeff_kernel(const float* __restrict__ Wq) {
    int e = blockIdx.x * 256 + threadIdx.x;
    int i = e >> 8, col = e & 255;
    int h = col >> 6, d = col & 63;
    const float* base = Wq + (size_t)i * 1024 + (h * 4) * 64 + d;
    g_Wqeff[e] = base[0] + base[64] + base[128] + base[192];
}

// ---------------------------------------------------------------------------
// Activation split: X fp32 [n] -> hi/lo bf16 (into g_Ahi/g_Alo)
// ---------------------------------------------------------------------------
__global__ void asplit_kernel(const float* __restrict__ X, int n) {
    int i = blockIdx.x * 256 + threadIdx.x;
    if (i < n) {
        float x = X[i];
        __nv_bfloat16 h = __float2bfloat16(x);
        g_Ahi[i] = h;
        g_Alo[i] = __float2bfloat16(x - __bfloat162float(h));
    }
}

// ---------------------------------------------------------------------------
// Weight transpose+split: W [K,N] fp32 -> T_hi/T_lo [N(+off), K] bf16
// ---------------------------------------------------------------------------
__global__ void wsplit_t_kernel(const float* __restrict__ W,
                                __nv_bfloat16* __restrict__ thi,
                                __nv_bfloat16* __restrict__ tlo,
                                int K, int N, int row_off) {
    int i = blockIdx.x * 256 + threadIdx.x;
    if (i < K * N) {
        int k = i / N, n = i % N;
        float x = W[i];
        __nv_bfloat16 h = __float2bfloat16(x);
        size_t o = (size_t)(row_off + n) * K + k;
        thi[o] = h;
        tlo[o] = __float2bfloat16(x - __bfloat162float(h));
    }
}

// ---------------------------------------------------------------------------
// HMMA GEMM (validated R11): C = A@B^T, 3-term bf16 split.
// ---------------------------------------------------------------------------
#define HS_PAD  72
#define HS_AHI  0
#define HS_ALO  (128 * HS_PAD)
#define HS_BHI  (2 * 128 * HS_PAD)
#define HS_BLO  (2 * 128 * HS_PAD + 64 * HS_PAD)
#define HS_TOTAL_BYTES ((2 * 128 * HS_PAD + 2 * 64 * HS_PAD) * 2)   // 55296

__global__ __launch_bounds__(256) void hmma_gemm_kernel(
    const __nv_bfloat16* __restrict__ Ahi, const __nv_bfloat16* __restrict__ Alo,
    const __nv_bfloat16* __restrict__ Bhi, const __nv_bfloat16* __restrict__ Blo,
    float* __restrict__ C, int K, int ldc)
{
    extern __shared__ __align__(16) __nv_bfloat16 hsm[];
    uint32_t smb = smem_u32(hsm);
    int tid = threadIdx.x, lane = tid & 31, warp = tid >> 5;
    int wm = (warp & 3) * 32;
    int wn = (warp >> 2) * 32;
    int n0 = blockIdx.x * 64, m0 = blockIdx.y * 128;

    float acc[2][4][4];
    #pragma unroll
    for (int i = 0; i < 2; i++)
        #pragma unroll
        for (int j = 0; j < 4; j++)
            #pragma unroll
            for (int k = 0; k < 4; k++) acc[i][j][k] = 0.f;

    uint32_t* smA_hi = (uint32_t*)(hsm + HS_AHI);
    uint32_t* smA_lo = (uint32_t*)(hsm + HS_ALO);
    uint32_t* smB_hi = (uint32_t*)(hsm + HS_BHI);
    uint32_t* smB_lo = (uint32_t*)(hsm + HS_BLO);
    int rs = K >> 1;

    int aRow = lane & 15, aKoff = (lane >> 4) << 3;
    int g = lane >> 3;
    int bRow = ((g >> 1) << 3) + (lane & 7), bKoff = (g & 1) << 3;

    int nchunks = K >> 6;
    for (int c = 0; c < nchunks; c++) {
        __syncthreads();
        const uint32_t* srcAh = (const uint32_t*)(Ahi + (size_t)m0 * K + c * 64);
        const uint32_t* srcAl = (const uint32_t*)(Alo + (size_t)m0 * K + c * 64);
        #pragma unroll
        for (int i = tid; i < 4096; i += 256) {
            int r = i >> 5, kp = i & 31;
            smA_hi[r * 36 + kp] = srcAh[(size_t)r * rs + kp];
            smA_lo[r * 36 + kp] = srcAl[(size_t)r * rs + kp];
        }
        const uint32_t* srcBh = (const uint32_t*)(Bhi + (size_t)n0 * K + c * 64);
        const uint32_t* srcBl = (const uint32_t*)(Blo + (size_t)n0 * K + c * 64);
        #pragma unroll
        for (int i = tid; i < 2048; i += 256) {
            int r = i >> 5, kp = i & 31;
            smB_hi[r * 36 + kp] = srcBh[(size_t)r * rs + kp];
            smB_lo[r * 36 + kp] = srcBl[(size_t)r * rs + kp];
        }
        __syncthreads();

        #pragma unroll
        for (int ks = 0; ks < 4; ks++) {
            int k0 = ks * 16;
            uint32_t ah[2][4], al[2][4], bh[4][2], bl[4][2];
            #pragma unroll
            for (int mt = 0; mt < 2; mt++) {
                uint32_t off = (uint32_t)(((wm + mt * 16 + aRow) * HS_PAD + k0 + aKoff) * 2);
                ldmx4(ah[mt], smb + HS_AHI * 2 + off);
                ldmx4(al[mt], smb + HS_ALO * 2 + off);
            }
            #pragma unroll
            for (int half = 0; half < 2; half++) {
                uint32_t off = (uint32_t)(((wn + half * 16 + bRow) * HS_PAD + k0 + bKoff) * 2);
                uint32_t t[4];
                ldmx4(t, smb + HS_BHI * 2 + off);
                bh[half * 2][0] = t[0]; bh[half * 2][1] = t[1];
                bh[half * 2 + 1][0] = t[2]; bh[half * 2 + 1][1] = t[3];
                ldmx4(t, smb + HS_BLO * 2 + off);
                bl[half * 2][0] = t[0]; bl[half * 2][1] = t[1];
                bl[half * 2 + 1][0] = t[2]; bl[half * 2 + 1][1] = t[3];
            }
            #pragma unroll
            for (int mt = 0; mt < 2; mt++)
                #pragma unroll
                for (int nt = 0; nt < 4; nt++) {
                    mma_bf16(acc[mt][nt], ah[mt], bh[nt]);
                    mma_bf16(acc[mt][nt], ah[mt], bl[nt]);
                    mma_bf16(acc[mt][nt], al[mt], bh[nt]);
                }
        }
    }

    int gid = lane >> 2, tig = lane & 3;
    #pragma unroll
    for (int mt = 0; mt < 2; mt++) {
        int row = m0 + wm + mt * 16 + gid;
        #pragma unroll
        for (int nt = 0; nt < 4; nt++) {
            int col = n0 + wn + nt * 8 + tig * 2;
            *(float2*)&C[(size_t)row * ldc + col]       = make_float2(acc[mt][nt][0], acc[mt][nt][1]);
            *(float2*)&C[(size_t)(row + 8) * ldc + col] = make_float2(acc[mt][nt][2], acc[mt][nt][3]);
        }
    }
}

// ---------------------------------------------------------------------------
// RoPE + bf16 hi/lo split (fused). Reads fp32 projection, writes split pair.
// One block per row, 128 threads = 4 heads * 32 pairs.
// ---------------------------------------------------------------------------
__global__ void rope_split_kernel(const float* __restrict__ buf,
                                  const int* __restrict__ coords, int ld,
                                  __nv_bfloat16* __restrict__ dsthi,
                                  __nv_bfloat16* __restrict__ dstlo)
{
    int row = blockIdx.x;
    int t = threadIdx.x;
    int head = t >> 5, pp = t & 31, axis = pp >> 4, fi = pp & 15;

    float af = (float)coords[row * 2 + axis] * c_invfreq[fi];
    float sn, cs;
    sincosf(af, &sn, &cs);

    const float* p = buf + (size_t)row * ld + head * 64 + pp * 2;
    float x1 = p[0], x2 = p[1];
    float y1 = x1 * cs - x2 * sn;
    float y2 = x1 * sn + x2 * cs;

    __nv_bfloat16 h1 = __float2bfloat16(y1), h2 = __float2bfloat16(y2);
    float l1 = y1 - __bfloat162float(h1);
    float l2 = y2 - __bfloat162float(h2);

    uint32_t idx = (uint32_t)row * 128 + head * 32 + pp;   // u32 index into [MROWS][256]
    uint32_t hv = ((uint32_t)__bfloat16_as_ushort(h2) << 16) | __bfloat16_as_ushort(h1);
    ((uint32_t*)dsthi)[idx] = hv;
    ((uint32_t*)dstlo)[idx] = cvt_pack(l1, l2);
}

// ---------------------------------------------------------------------------
// V transpose + split: g_KV V-half -> Vt[bh][dim][seq] hi/lo bf16
// ---------------------------------------------------------------------------
__global__ void vt_split_kernel(const float* __restrict__ kv,
                                __nv_bfloat16* __restrict__ vhi,
                                __nv_bfloat16* __restrict__ vlo)
{
    int i = blockIdx.x * 256 + threadIdx.x;     // 0 .. 2M-1
    int s = i & 2047, d = (i >> 11) & 63, bh = i >> 17;
    int b = bh >> 2, h = bh & 3;
    float x = kv[((size_t)b * SEQ + s) * 512 + 256 + h * 64 + d];
    __nv_bfloat16 hh = __float2bfloat16(x);
    vhi[i] = hh;
    vlo[i] = __float2bfloat16(x - __bfloat162float(hh));
}

// ---------------------------------------------------------------------------
// Tensor-core flash attention (3-term bf16 split on both QK^T and PV).
// Block: 128 queries x 64-key tiles, 8 warps x 16 queries. grid (16, 16).
// Smem (bf16 elems): Qhi[128][72], Qlo, Khi[64][72], Klo, Vthi[64][72], Vtlo
// ---------------------------------------------------------------------------
#define AT_QH 0
#define AT_QL 9216
#define AT_KH 18432
#define AT_KL 23040
#define AT_VH 27648
#define AT_VL 32256
#define AT_BYTES (36864 * 2)

__global__ __launch_bounds__(256) void attn_mma_kernel(
    const __nv_bfloat16* __restrict__ qhi, const __nv_bfloat16* __restrict__ qlo,
    const __nv_bfloat16* __restrict__ khi, const __nv_bfloat16* __restrict__ klo,
    const __nv_bfloat16* __restrict__ vhi, const __nv_bfloat16* __restrict__ vlo)
{
    extern __shared__ __align__(16) __nv_bfloat16 sm2[];
    uint32_t smb = smem_u32(sm2);
    uint32_t* s32 = (uint32_t*)sm2;
    int tid = threadIdx.x, lane = tid & 31, w = tid >> 5;
    int bh = blockIdx.y;               // b*NH + h
    int b = bh >> 2, h = bh & 3;
    int qbase = blockIdx.x * 128;

    // Load Q tiles once (hi/lo), [128][72]
    const uint32_t* q32h = (const uint32_t*)qhi;
    const uint32_t* q32l = (const uint32_t*)qlo;
    for (int i = tid; i < 4096; i += 256) {
        int r = i >> 5, kp = i & 31;
        size_t src = (size_t)(b * SEQ + qbase + r) * 128 + h * 32 + kp;
        s32[(AT_QH >> 1) + r * 36 + kp] = q32h[src];
        s32[(AT_QL >> 1) + r * 36 + kp] = q32l[src];
    }

    int gid = lane >> 2, tig = lane & 3;
    int aRow = lane & 15, aK8 = (lane >> 4) << 3;
    int g4 = lane >> 3;
    int bRow = ((g4 >> 1) << 3) + (lane & 7), bK8 = (g4 & 1) << 3;

    float mrow0 = -INFINITY, mrow1 = -INFINITY;
    float lrow0 = 0.f, lrow1 = 0.f;
    float oacc[8][4];
    #pragma unroll
    for (int i = 0; i < 8; i++)
        #pragma unroll
        for (int j = 0; j < 4; j++) oacc[i][j] = 0.f;

    const uint32_t* k32h = (const uint32_t*)khi;
    const uint32_t* k32l = (const uint32_t*)klo;
    const uint32_t* v32h = (const uint32_t*)vhi;
    const uint32_t* v32l = (const uint32_t*)vlo;

    for (int kt = 0; kt < 32; kt++) {
        __syncthreads();
        int kb = kt * 64;
        // K tile [64 keys][72 dims] and Vt tile [64 dims][72 keys]
        for (int i = tid; i < 2048; i += 256) {
            int r = i >> 5, kp = i & 31;
            size_t ksrc = (size_t)(b * SEQ + kb + r) * 128 + h * 32 + kp;
            s32[(AT_KH >> 1) + r * 36 + kp] = k32h[ksrc];
            s32[(AT_KL >> 1) + r * 36 + kp] = k32l[ksrc];
            size_t vsrc = (size_t)(bh * 64 + r) * 1024 + (kb >> 1) + kp;
            s32[(AT_VH >> 1) + r * 36 + kp] = v32h[vsrc];
            s32[(AT_VL >> 1) + r * 36 + kp] = v32l[vsrc];
        }
        __syncthreads();

        // ---- S = Q @ K^T (3-term split), warp: 16 q x 64 k ----
        float sacc[8][4];
        #pragma unroll
        for (int i = 0; i < 8; i++)
            #pragma unroll
            for (int j = 0; j < 4; j++) sacc[i][j] = 0.f;

        #pragma unroll
        for (int ks = 0; ks < 4; ks++) {
            uint32_t qh4[4], ql4[4];
            uint32_t qoff = (uint32_t)(((w * 16 + aRow) * 72 + ks * 16 + aK8) * 2);
            ldmx4(qh4, smb + AT_QH * 2 + qoff);
            ldmx4(ql4, smb + AT_QL * 2 + qoff);
            #pragma unroll
            for (int np = 0; np < 4; np++) {
                uint32_t off = (uint32_t)(((np * 16 + bRow) * 72 + ks * 16 + bK8) * 2);
                uint32_t th[4], tl[4];
                ldmx4(th, smb + AT_KH * 2 + off);
                ldmx4(tl, smb + AT_KL * 2 + off);
                uint32_t bh0[2] = {th[0], th[1]}, bh1[2] = {th[2], th[3]};
                uint32_t bl0[2] = {tl[0], tl[1]}, bl1[2] = {tl[2], tl[3]};
                mma_bf16(sacc[2 * np],     qh4, bh0);
                mma_bf16(sacc[2 * np],     qh4, bl0);
                mma_bf16(sacc[2 * np],     ql4, bh0);
                mma_bf16(sacc[2 * np + 1], qh4, bh1);
                mma_bf16(sacc[2 * np + 1], qh4, bl1);
                mma_bf16(sacc[2 * np + 1], ql4, bh1);
            }
        }

        // ---- online softmax (rows gid / gid+8 of warp's 16 queries) ----
        float rmax0 = -INFINITY, rmax1 = -INFINITY;
        #pragma unroll
        for (int np = 0; np < 8; np++) {
            #pragma unroll
            for (int j = 0; j < 4; j++) sacc[np][j] *= 0.125f;
            rmax0 = fmaxf(rmax0, fmaxf(sacc[np][0], sacc[np][1]));
            rmax1 = fmaxf(rmax1, fmaxf(sacc[np][2], sacc[np][3]));
        }
        rmax0 = fmaxf(rmax0, __shfl_xor_sync(0xffffffffu, rmax0, 1));
        rmax0 = fmaxf(rmax0, __shfl_xor_sync(0xffffffffu, rmax0, 2));
        rmax1 = fmaxf(rmax1, __shfl_xor_sync(0xffffffffu, rmax1, 1));
        rmax1 = fmaxf(rmax1, __shfl_xor_sync(0xffffffffu, rmax1, 2));

        float mn0 = fmaxf(mrow0, rmax0), mn1 = fmaxf(mrow1, rmax1);
        float al0 = __expf(mrow0 - mn0), al1 = __expf(mrow1 - mn1);
        mrow0 = mn0; mrow1 = mn1;

        float rsum0 = 0.f, rsum1 = 0.f;
        #pragma unroll
        for (int np = 0; np < 8; np++) {
            sacc[np][0] = __expf(sacc[np][0] - mn0);
            sacc[np][1] = __expf(sacc[np][1] - mn0);
            sacc[np][2] = __expf(sacc[np][2] - mn1);
            sacc[np][3] = __expf(sacc[np][3] - mn1);
            rsum0 += sacc[np][0] + sacc[np][1];
            rsum1 += sacc[np][2] + sacc[np][3];
        }
        rsum0 += __shfl_xor_sync(0xffffffffu, rsum0, 1);
        rsum0 += __shfl_xor_sync(0xffffffffu, rsum0, 2);
        rsum1 += __shfl_xor_sync(0xffffffffu, rsum1, 1);
        rsum1 += __shfl_xor_sync(0xffffffffu, rsum1, 2);
        lrow0 = lrow0 * al0 + rsum0;
        lrow1 = lrow1 * al1 + rsum1;

        #pragma unroll
        for (int np = 0; np < 8; np++) {
            oacc[np][0] *= al0; oacc[np][1] *= al0;
            oacc[np][2] *= al1; oacc[np][3] *= al1;
        }

        // ---- O += P @ V (3-term split), P packed from score fragments ----
        #pragma unroll
        for (int kk = 0; kk < 4; kk++) {
            // A fragments: k-step kk <- score tiles 2kk (c0..c3), 2kk+1 (c0..c3)
            float p00 = sacc[2 * kk][0],     p01 = sacc[2 * kk][1];
            float p02 = sacc[2 * kk][2],     p03 = sacc[2 * kk][3];
            float p10 = sacc[2 * kk + 1][0], p11 = sacc[2 * kk + 1][1];
            float p12 = sacc[2 * kk + 1][2], p13 = sacc[2 * kk + 1][3];
            uint32_t pah[4], pal[4];
            pah[0] = prmt_pack(p00, p01);
            pah[1] = prmt_pack(p02, p03);
            pah[2] = prmt_pack(p10, p11);
            pah[3] = prmt_pack(p12, p13);
            pal[0] = cvt_pack(p00 - trunc_bf(p00), p01 - trunc_bf(p01));
            pal[1] = cvt_pack(p02 - trunc_bf(p02), p03 - trunc_bf(p03));
            pal[2] = cvt_pack(p10 - trunc_bf(p10), p11 - trunc_bf(p11));
            pal[3] = cvt_pack(p12 - trunc_bf(p12), p13 - trunc_bf(p13));

            #pragma unroll
            for (int np = 0; np < 4; np++) {
                uint32_t off = (uint32_t)(((np * 16 + bRow) * 72 + kk * 16 + bK8) * 2);
                uint32_t th[4], tl[4];
                ldmx4(th, smb + AT_VH * 2 + off);
                ldmx4(tl, smb + AT_VL * 2 + off);
                uint32_t vh0[2] = {th[0], th[1]}, vh1[2] = {th[2], th[3]};
                uint32_t vl0[2] = {tl[0], tl[1]}, vl1[2] = {tl[2], tl[3]};
                mma_bf16(oacc[2 * np],     pah, vh0);
                mma_bf16(oacc[2 * np],     pah, vl0);
                mma_bf16(oacc[2 * np],     pal, vh0);
                mma_bf16(oacc[2 * np + 1], pah, vh1);
                mma_bf16(oacc[2 * np + 1], pah, vl1);
                mma_bf16(oacc[2 * np + 1], pal, vh1);
            }
        }
    }

    // Epilogue: normalize and write
    float inv0 = 1.0f / lrow0, inv1 = 1.0f / lrow1;
    int row0 = qbase + w * 16 + gid;
    #pragma unroll
    for (int np = 0; np < 8; np++) {
        int col = h * 64 + np * 8 + tig * 2;
        *(float2*)&g_AO[(size_t)(b * SEQ + row0) * 256 + col] =
            make_float2(oacc[np][0] * inv0, oacc[np][1] * inv0);
        *(float2*)&g_AO[(size_t)(b * SEQ + row0 + 8) * 256 + col] =
            make_float2(oacc[np][2] * inv1, oacc[np][3] * inv1);
    }
}

// ---------------------------------------------------------------------------
extern "C" void kernel_launch(void* const* d_in, const int* in_sizes, int n_in,
                              void* d_out, int out_size) {
    const float* q   = (const float*)d_in[0];
    const int*   qc  = (const int*)  d_in[1];
    const float* kv  = (const float*)d_in[2];
    const int*   kvc = (const int*)  d_in[3];
    const float* Wq  = (const float*)d_in[4];
    const float* Wk  = (const float*)d_in[5];
    const float* Wv  = (const float*)d_in[6];
    const float* Wo  = (const float*)d_in[7];
    float* out = (float*)d_out;

    float *pWqeff, *pQS, *pKV, *pAO;
    cudaGetSymbolAddress((void**)&pWqeff, g_Wqeff);
    cudaGetSymbolAddress((void**)&pQS,    g_QS);
    cudaGetSymbolAddress((void**)&pKV,    g_KV);
    cudaGetSymbolAddress((void**)&pAO,    g_AO);
    __nv_bfloat16 *pAhi, *pAlo, *pWqTh, *pWqTl, *pWkvTh, *pWkvTl, *pWoTh, *pWoTl;
    cudaGetSymbolAddress((void**)&pAhi,   g_Ahi);
    cudaGetSymbolAddress((void**)&pAlo,   g_Alo);
    cudaGetSymbolAddress((void**)&pWqTh,  g_WqT_hi);
    cudaGetSymbolAddress((void**)&pWqTl,  g_WqT_lo);
    cudaGetSymbolAddress((void**)&pWkvTh, g_WkvT_hi);
    cudaGetSymbolAddress((void**)&pWkvTl, g_WkvT_lo);
    cudaGetSymbolAddress((void**)&pWoTh,  g_WoT_hi);
    cudaGetSymbolAddress((void**)&pWoTl,  g_WoT_lo);

    const int RM = MROWS * 256;   // 2M elements per attention operand
    __nv_bfloat16 *qhi = pAhi,          *qlo = pAlo;
    __nv_bfloat16 *khi = pAhi + RM,     *klo = pAlo + RM;
    __nv_bfloat16 *vhi = pAhi + 2 * RM, *vlo = pAlo + 2 * RM;

    cudaFuncSetAttribute(hmma_gemm_kernel, cudaFuncAttributeMaxDynamicSharedMemorySize, HS_TOTAL_BYTES);
    cudaFuncSetAttribute(attn_mma_kernel,  cudaFuncAttributeMaxDynamicSharedMemorySize, AT_BYTES);

    // 1) weight prep
    wqeff_kernel<<<1024, 256>>>(Wq);
    wsplit_t_kernel<<<(1024 * 256 + 255) / 256, 256>>>(pWqeff, pWqTh, pWqTl, 1024, 256, 0);
    wsplit_t_kernel<<<(1024 * 256 + 255) / 256, 256>>>(Wk, pWkvTh, pWkvTl, 1024, 256, 0);
    wsplit_t_kernel<<<(1024 * 256 + 255) / 256, 256>>>(Wv, pWkvTh, pWkvTl, 1024, 256, 256);
    wsplit_t_kernel<<<(256 * 1024 + 255) / 256, 256>>>(Wo, pWoTh, pWoTl, 256, 1024, 0);

    // 2) KV projection (fused K|V, N=512)
    asplit_kernel<<<(MROWS * 1024 + 255) / 256, 256>>>(kv, MROWS * 1024);
    hmma_gemm_kernel<<<dim3(8, 64), 256, HS_TOTAL_BYTES>>>(pAhi, pAlo, pWkvTh, pWkvTl, pKV, 1024, 512);

    // 3) Q projection (group-summed, N=256)
    asplit_kernel<<<(MROWS * 1024 + 255) / 256, 256>>>(q, MROWS * 1024);
    hmma_gemm_kernel<<<dim3(4, 64), 256, HS_TOTAL_BYTES>>>(pAhi, pAlo, pWqTh, pWqTl, pQS, 1024, 256);

    // 4) RoPE fused with bf16 hi/lo split; V transpose+split
    rope_split_kernel<<<MROWS, 128>>>(pQS, qc,  256, qhi, qlo);
    rope_split_kernel<<<MROWS, 128>>>(pKV, kvc, 512, khi, klo);
    vt_split_kernel<<<(MROWS * 256 + 255) / 256, 256>>>(pKV, vhi, vlo);

    // 5) tensor-core flash attention
    attn_mma_kernel<<<dim3(16, 16), 256, AT_BYTES>>>(qhi, qlo, khi, klo, vhi, vlo);

    // 6) output projection (K=256, N=1024)
    asplit_kernel<<<(MROWS * 256 + 255) / 256, 256>>>(pAO, MROWS * 256);
    hmma_gemm_kernel<<<dim3(16, 64), 256, HS_TOTAL_BYTES>>>(pAhi, pAlo, pWoTh, pWoTl, out, 256, 1024);
}